// round 7
// baseline (speedup 1.0000x reference)
#include <cuda_runtime.h>
#include <cuda_fp16.h>
#include <cstdint>

#define BATCH 512
#define SEQLEN 512
#define INSZ 64
#define RES 1024
#define OUTSZ 64

// ---------------- static device buffers (no allocation allowed) -------------
__device__ float g_state[BATCH * RES];              // fp32 state, in-place
__device__ __half g_shi[2][BATCH * RES];            // state hi (fp16), ping-pong
__device__ __half g_slo[2][BATCH * RES];            // state lo (fp16), ping-pong
__device__ __half g_w16[RES * RES];                 // W_res in fp16
__device__ __half g_win16[INSZ * RES];              // W_in in fp16
__device__ __half g_xhi[BATCH * SEQLEN * INSZ];     // input hi
__device__ __half g_xlo[BATCH * SEQLEN * INSZ];     // input lo
__device__ unsigned g_flag[8][16];                  // per (rowgrp, coltile) step counter

// ---------------- prep kernels ---------------------------------------------
__global__ void split_kernel(const float* __restrict__ src,
                             __half* __restrict__ hi,
                             __half* __restrict__ lo, int n) {
    int i = blockIdx.x * blockDim.x + threadIdx.x;
    int stride = gridDim.x * blockDim.x;
    for (; i < n; i += stride) {
        float v = src[i];
        __half h = __float2half(v);
        hi[i] = h;
        lo[i] = __float2half(v - __half2float(h));
    }
}

__global__ void cvt_kernel(const float* __restrict__ src,
                           __half* __restrict__ dst, int n) {
    int i = blockIdx.x * blockDim.x + threadIdx.x;
    int stride = gridDim.x * blockDim.x;
    for (; i < n; i += stride) dst[i] = __float2half(src[i]);
}

__global__ void zero_kernel() {
    int i = blockIdx.x * blockDim.x + threadIdx.x;
    int stride = gridDim.x * blockDim.x;
    if (i < 128) ((unsigned*)g_flag)[i] = 0;     // reset flags every launch/replay
    const __half z = __float2half(0.0f);
    for (int k = i; k < BATCH * RES; k += stride) {
        g_state[k] = 0.0f;
        g_shi[0][k] = z;
        g_slo[0][k] = z;
    }
}

// ---------------- persistent ESN kernel -------------------------------------
// One launch runs all 512 steps. 128 resident CTAs (grid 128 <= 148 SMs).
// CTA (r,c): rows [64r,64r+64) x cols [64c,64c+64). Row groups are independent
// chains; within a row group, cross-CTA sync via monotonic flag counters:
// producer (r,c) sets g_flag[r][c]=s+1 after its step-s epilogue; consumer
// spin-waits g_flag[r][kb]>=s before loading k-block kb of step s.
// Per step: Y = Shi@W16 + Slo@W16 + xhi@Win16 + xlo@Win16 (2-product fp16
// split), 17 K-blocks of 64 (input block first: no dependency), 4-stage
// cp.async ring, warp tile 16x32 via mma.sync.m16n8k16 fp16.
#define NIT 17
#define STAGES 4
#define STAGE_BYTES 24576      // Ahi 8K | Alo 8K | B 8K
#define SA_LO 8192
#define SB    16384

__device__ __forceinline__ uint32_t sw_off(int row, int colByte) {
    // 128B rows, XOR-swizzled 16B chunks: conflict-free cp.async + ldmatrix
    return (uint32_t)(row * 128 + ((((colByte >> 4) ^ (row & 7)) << 4) | (colByte & 15)));
}

__global__ __launch_bounds__(256) void esn_kernel() {
    extern __shared__ char smem[];
    const int tid  = threadIdx.x;
    const int lane = tid & 31;
    const int warp = tid >> 5;
    const int warpM = warp & 3;     // 4 warps along M (16 rows each)
    const int warpN = warp >> 2;    // 2 warps along N (32 cols each)
    const int r = blockIdx.x >> 4;  // row group 0..7
    const int c = blockIdx.x & 15;  // col tile  0..15
    const int rowBase = r * 64;
    const int colBase = c * 64;

    const uint32_t smem_u32 = (uint32_t)__cvta_generic_to_shared(smem);

    for (int s = 0; s < SEQLEN; s++) {
        const int pp = s & 1;

        // issue K-block for pipeline position i (i=0 -> input block, else i-1)
        auto issue = [&](int i) {
            const int kb = (i == 0) ? 16 : i - 1;
            if (kb < 16 && s > 0) {
                const unsigned* fl = &g_flag[r][kb];
                unsigned v;
                do {
                    asm volatile("ld.volatile.global.u32 %0, [%1];"
                                 : "=r"(v) : "l"(fl));
                } while ((int)v < s);
                __threadfence();   // acquire: order flag read before data reads
            }
            const __half *Ahi, *Alo, *B;
            long long ldA;
            if (kb < 16) {
                int k0 = kb << 6;
                Ahi = g_shi[pp] + k0;
                Alo = g_slo[pp] + k0;
                ldA = RES;
                B = g_w16 + (long long)k0 * RES;
            } else {
                Ahi = g_xhi + (long long)s * INSZ;
                Alo = g_xlo + (long long)s * INSZ;
                ldA = (long long)SEQLEN * INSZ;
                B = g_win16;
            }
            uint32_t base = smem_u32 + (i & 3) * STAGE_BYTES;
            #pragma unroll
            for (int q = 0; q < 2; q++) {       // A tiles: 64x64 fp16 each
                int ch = tid + q * 256;
                int rr = ch >> 3, kc = ch & 7;
                long long aoff = (long long)(rowBase + rr) * ldA + kc * 8;
                uint32_t so = sw_off(rr, kc * 16);
                asm volatile("cp.async.cg.shared.global [%0], [%1], 16;\n"
                             :: "r"(base + so), "l"((const void*)(Ahi + aoff)));
                asm volatile("cp.async.cg.shared.global [%0], [%1], 16;\n"
                             :: "r"(base + SA_LO + so), "l"((const void*)(Alo + aoff)));
            }
            #pragma unroll
            for (int q = 0; q < 2; q++) {       // B tile
                int ch = tid + q * 256;
                int kr = ch >> 3, nc = ch & 7;
                long long boff = (long long)kr * RES + colBase + nc * 8;
                uint32_t so = sw_off(kr, nc * 16);
                asm volatile("cp.async.cg.shared.global [%0], [%1], 16;\n"
                             :: "r"(base + SB + so), "l"((const void*)(B + boff)));
            }
        };

        float acc[4][4];
        #pragma unroll
        for (int j = 0; j < 4; j++)
            #pragma unroll
            for (int q = 0; q < 4; q++) acc[j][q] = 0.0f;

        issue(0); asm volatile("cp.async.commit_group;\n" ::);
        issue(1); asm volatile("cp.async.commit_group;\n" ::);
        issue(2); asm volatile("cp.async.commit_group;\n" ::);

        for (int i = 0; i < NIT; i++) {
            asm volatile("cp.async.wait_group %0;\n" :: "n"(2));
            __syncthreads();
            if (i + 3 < NIT) issue(i + 3);
            asm volatile("cp.async.commit_group;\n" ::);

            uint32_t base = smem_u32 + (i & 3) * STAGE_BYTES;

            #pragma unroll
            for (int kf = 0; kf < 4; kf++) {       // 4 x k16 per block
                uint32_t ahi[4], alo[4];
                {
                    int row = warpM * 16 + (lane & 15);
                    int colByte = kf * 32 + (lane >> 4) * 16;
                    uint32_t so = sw_off(row, colByte);
                    asm volatile("ldmatrix.sync.aligned.m8n8.x4.shared.b16 {%0,%1,%2,%3}, [%4];"
                        : "=r"(ahi[0]), "=r"(ahi[1]), "=r"(ahi[2]), "=r"(ahi[3])
                        : "r"(base + so));
                    asm volatile("ldmatrix.sync.aligned.m8n8.x4.shared.b16 {%0,%1,%2,%3}, [%4];"
                        : "=r"(alo[0]), "=r"(alo[1]), "=r"(alo[2]), "=r"(alo[3])
                        : "r"(base + SA_LO + so));
                }
                uint32_t b[2][4];
                #pragma unroll
                for (int nh = 0; nh < 2; nh++) {
                    int krow = kf * 16 + (lane & 7) + ((lane >> 3) & 1) * 8;
                    int colByte = (warpN * 32 + nh * 16 + (lane >> 4) * 8) * 2;
                    uint32_t so = sw_off(krow, colByte);
                    asm volatile("ldmatrix.sync.aligned.m8n8.x4.trans.shared.b16 {%0,%1,%2,%3}, [%4];"
                        : "=r"(b[nh][0]), "=r"(b[nh][1]), "=r"(b[nh][2]), "=r"(b[nh][3])
                        : "r"(base + SB + so));
                }
                #pragma unroll
                for (int j = 0; j < 4; j++) {
                    uint32_t b0 = b[j >> 1][(j & 1) * 2], b1 = b[j >> 1][(j & 1) * 2 + 1];
                    asm volatile(
                        "mma.sync.aligned.m16n8k16.row.col.f32.f16.f16.f32 "
                        "{%0,%1,%2,%3}, {%4,%5,%6,%7}, {%8,%9}, {%0,%1,%2,%3};"
                        : "+f"(acc[j][0]), "+f"(acc[j][1]), "+f"(acc[j][2]), "+f"(acc[j][3])
                        : "r"(ahi[0]), "r"(ahi[1]), "r"(ahi[2]), "r"(ahi[3]), "r"(b0), "r"(b1));
                    asm volatile(
                        "mma.sync.aligned.m16n8k16.row.col.f32.f16.f16.f32 "
                        "{%0,%1,%2,%3}, {%4,%5,%6,%7}, {%8,%9}, {%0,%1,%2,%3};"
                        : "+f"(acc[j][0]), "+f"(acc[j][1]), "+f"(acc[j][2]), "+f"(acc[j][3])
                        : "r"(alo[0]), "r"(alo[1]), "r"(alo[2]), "r"(alo[3]), "r"(b0), "r"(b1));
                }
            }
        }

        // ---- epilogue: leaky tanh; in-place fp32 state (tile-exclusive),
        //      emit fp16 hi/lo for next step ----
        __half* __restrict__ shiN = g_shi[pp ^ 1];
        __half* __restrict__ sloN = g_slo[pp ^ 1];
        #pragma unroll
        for (int j = 0; j < 4; j++)
            #pragma unroll
            for (int h = 0; h < 2; h++) {
                int row = rowBase + warpM * 16 + (lane >> 2) + 8 * h;
                int col = colBase + warpN * 32 + j * 8 + (lane & 3) * 2;
                long long idx = (long long)row * RES + col;
                float2 sold = *reinterpret_cast<float2*>(&g_state[idx]);
                float n0 = 0.5f * sold.x + 0.5f * tanhf(acc[j][h * 2 + 0]);
                float n1 = 0.5f * sold.y + 0.5f * tanhf(acc[j][h * 2 + 1]);
                *reinterpret_cast<float2*>(&g_state[idx]) = make_float2(n0, n1);
                __half h0 = __float2half(n0);
                __half h1 = __float2half(n1);
                __half2 hv; hv.x = h0; hv.y = h1;
                __half2 lv;
                lv.x = __float2half(n0 - __half2float(h0));
                lv.y = __float2half(n1 - __half2float(h1));
                *reinterpret_cast<__half2*>(&shiN[idx]) = hv;
                *reinterpret_cast<__half2*>(&sloN[idx]) = lv;
            }

        // all threads' epilogue stores + all smem reads done before flag/reuse
        __syncthreads();
        if (tid == 0) {
            __threadfence();                       // release: publish state tiles
            asm volatile("st.volatile.global.u32 [%0], %1;"
                         :: "l"(&g_flag[r][c]), "r"(s + 1));
        }
    }
}

// ---------------- output GEMM ----------------------------------------------
__global__ __launch_bounds__(64) void output_kernel(
    const float* __restrict__ Wout, float* __restrict__ out) {
    __shared__ float srow[RES];
    const int b = blockIdx.x;
    const int j = threadIdx.x;
    for (int k = j; k < RES; k += 64) srow[k] = g_state[b * RES + k];
    __syncthreads();
    float sum = 0.0f;
    #pragma unroll 8
    for (int k = 0; k < RES; k++)
        sum = fmaf(srow[k], Wout[k * OUTSZ + j], sum);
    out[b * OUTSZ + j] = sum;
}

// ---------------- launch ----------------------------------------------------
extern "C" void kernel_launch(void* const* d_in, const int* in_sizes, int n_in,
                              void* d_out, int out_size) {
    const float* input = (const float*)d_in[0];   // [512,512,64]
    const float* Wres  = (const float*)d_in[1];   // [1024,1024]
    const float* Win   = (const float*)d_in[2];   // [64,1024]
    const float* Wout  = (const float*)d_in[3];   // [1024,64]
    float* out = (float*)d_out;

    void *w16, *win16, *xhi, *xlo;
    cudaGetSymbolAddress(&w16,   g_w16);
    cudaGetSymbolAddress(&win16, g_win16);
    cudaGetSymbolAddress(&xhi,   g_xhi);
    cudaGetSymbolAddress(&xlo,   g_xlo);

    cudaFuncSetAttribute(esn_kernel,
                         cudaFuncAttributeMaxDynamicSharedMemorySize,
                         STAGES * STAGE_BYTES);

    cvt_kernel<<<2048, 256>>>(Wres, (__half*)w16, RES * RES);
    cvt_kernel<<<256, 256>>>(Win, (__half*)win16, INSZ * RES);
    split_kernel<<<8192, 256>>>(input, (__half*)xhi, (__half*)xlo,
                                BATCH * SEQLEN * INSZ);
    zero_kernel<<<1024, 512>>>();

    esn_kernel<<<128, 256, STAGES * STAGE_BYTES>>>();   // one persistent launch

    output_kernel<<<BATCH, 64>>>(Wout, out);
}

// round 8
// speedup vs baseline: 2.0697x; 2.0697x over previous
#include <cuda_runtime.h>
#include <cuda_fp16.h>
#include <cstdint>

#define BATCH 512
#define SEQLEN 512
#define INSZ 64
#define RES 1024
#define OUTSZ 64

// ---------------- static device buffers (no allocation allowed) -------------
__device__ float g_state[BATCH * RES];              // fp32 state, in-place
__device__ __half g_shi[2][BATCH * RES];            // state hi (fp16), ping-pong
__device__ __half g_slo[2][BATCH * RES];            // state lo (fp16), ping-pong
__device__ __half g_w16[RES * RES];                 // W_res in fp16
__device__ __half g_win16[INSZ * RES];              // W_in in fp16
__device__ __half g_xhi[BATCH * SEQLEN * INSZ];     // input hi
__device__ __half g_xlo[BATCH * SEQLEN * INSZ];     // input lo

// ---------------- merged prep kernel (ONE launch) ---------------------------
__global__ void prep_kernel(const float* __restrict__ input,
                            const float* __restrict__ Wres,
                            const float* __restrict__ Win) {
    int i = blockIdx.x * blockDim.x + threadIdx.x;
    int stride = gridDim.x * blockDim.x;
    const __half z = __float2half(0.0f);
    for (int k = i; k < BATCH * SEQLEN * INSZ; k += stride) {
        float v = input[k];
        __half h = __float2half(v);
        g_xhi[k] = h;
        g_xlo[k] = __float2half(v - __half2float(h));
        if (k < RES * RES) g_w16[k] = __float2half(Wres[k]);
        if (k < INSZ * RES) g_win16[k] = __float2half(Win[k]);
        if (k < BATCH * RES) {
            g_state[k] = 0.0f;
            g_shi[0][k] = z;
            g_slo[0][k] = z;
        }
    }
}

// ---------------- fast tanh (ex2 + rcp approx; abs err ~1e-6) ---------------
__device__ __forceinline__ float fast_tanhf(float x) {
    float e;
    asm("ex2.approx.f32 %0, %1;" : "=f"(e) : "f"(x * 2.8853900817779268f)); // 2x*log2(e)
    float r;
    asm("rcp.approx.f32 %0, %1;" : "=f"(r) : "f"(e + 1.0f));
    return fmaf(-2.0f, r, 1.0f);            // 1 - 2/(e^{2x}+1)
}

// ---------------- step kernel ----------------------------------------------
// Y = Shi@W16 + Slo@W16 + xhi@Win16 + xlo@Win16 (2-product fp16 split).
// BK=128 K-blocks (8 of state/W + 1 half-size input/Win) = 9 iterations.
// Each K-block stored as two 64-wide subtiles (128B-row swizzle preserved).
// BM=BN=64, 256 threads (8 warps, 4Mx2N), warp tile 16x32, 3-slot ring.
#define NIT 9
#define NSLOT 3
#define STAGE_BYTES 49152      // Ahi 16K | Alo 16K | B 16K
#define A_LO_OFF 16384
#define B_OFF    32768

__device__ __forceinline__ uint32_t sw_off(int row, int colByte) {
    // 128B rows, XOR-swizzled 16B chunks: conflict-free cp.async + ldmatrix
    return (uint32_t)(row * 128 + ((((colByte >> 4) ^ (row & 7)) << 4) | (colByte & 15)));
}

__global__ __launch_bounds__(256) void step_kernel(int t) {
    extern __shared__ char smem[];
    const int tid  = threadIdx.x;
    const int lane = tid & 31;
    const int warp = tid >> 5;
    const int warpM = warp & 3;     // 4 warps along M (16 rows each)
    const int warpN = warp >> 2;    // 2 warps along N (32 cols each)
    const int rowBase = blockIdx.y * 64;   // batch rows
    const int colBase = blockIdx.x * 64;   // reservoir cols
    const int pp = t & 1;

    const uint32_t smem_u32 = (uint32_t)__cvta_generic_to_shared(smem);

    // issue K-block kk into slot kk%3.  kk<8: BK=128 state/W.  kk==8: BK=64 input.
    auto issue = [&](int kk) {
        const __half *Ahi, *Alo, *B;
        long long ldA;
        int kch;                                   // 16B chunks per A row (BK/8)
        if (kk < 8) {
            int k0 = kk << 7;
            Ahi = g_shi[pp] + k0;
            Alo = g_slo[pp] + k0;
            ldA = RES;
            B = g_w16 + (long long)k0 * RES;
            kch = 16;
        } else {
            Ahi = g_xhi + (long long)t * INSZ;
            Alo = g_xlo + (long long)t * INSZ;
            ldA = (long long)SEQLEN * INSZ;
            B = g_win16;
            kch = 8;
        }
        uint32_t base = smem_u32 + (kk % NSLOT) * STAGE_BYTES;
        const int nl = kch >> 2;                   // 4 (BK=128) or 2 (BK=64)
        for (int i = 0; i < nl; i++) {             // A tiles: 64 rows x kch chunks
            int c = tid + i * 256;
            int r = c / kch, kc = c % kch;
            uint32_t so = (uint32_t)(kc >> 3) * 8192 + sw_off(r, (kc & 7) * 16);
            long long aoff = (long long)(rowBase + r) * ldA + kc * 8;
            asm volatile("cp.async.cg.shared.global [%0], [%1], 16;\n"
                         :: "r"(base + so), "l"((const void*)(Ahi + aoff)));
            asm volatile("cp.async.cg.shared.global [%0], [%1], 16;\n"
                         :: "r"(base + A_LO_OFF + so), "l"((const void*)(Alo + aoff)));
        }
        for (int i = 0; i < nl; i++) {             // B tile: BK rows x 8 chunks
            int c = tid + i * 256;
            int kr = c >> 3, nc = c & 7;
            uint32_t so = (uint32_t)(kr >> 6) * 8192 + sw_off(kr & 63, nc * 16);
            long long boff = (long long)kr * RES + colBase + nc * 8;
            asm volatile("cp.async.cg.shared.global [%0], [%1], 16;\n"
                         :: "r"(base + B_OFF + so), "l"((const void*)(B + boff)));
        }
    };

    float acc[4][4];                 // warp tile 16x32: 4 n8 groups x 4 regs
    #pragma unroll
    for (int j = 0; j < 4; j++)
        #pragma unroll
        for (int q = 0; q < 4; q++) acc[j][q] = 0.0f;

    issue(0); asm volatile("cp.async.commit_group;\n" ::);
    issue(1); asm volatile("cp.async.commit_group;\n" ::);

    for (int kk = 0; kk < NIT; kk++) {
        asm volatile("cp.async.wait_group %0;\n" :: "n"(1));  // slot kk resident
        __syncthreads();            // all warps done with slot (kk-1)%3 reads
        if (kk + 2 < NIT) issue(kk + 2);
        asm volatile("cp.async.commit_group;\n" ::);

        uint32_t base = smem_u32 + (kk % NSLOT) * STAGE_BYTES;
        const int nkf = (kk < 8) ? 8 : 4;

        #pragma unroll 8
        for (int kf = 0; kf < nkf; kf++) {       // k16 slices
            const uint32_t sub = (uint32_t)(kf >> 2) * 8192;
            const int kfl = kf & 3;
            uint32_t ahi[4], alo[4];
            {
                int row = warpM * 16 + (lane & 15);
                int colByte = kfl * 32 + (lane >> 4) * 16;
                uint32_t so = sw_off(row, colByte);
                asm volatile("ldmatrix.sync.aligned.m8n8.x4.shared.b16 {%0,%1,%2,%3}, [%4];"
                    : "=r"(ahi[0]), "=r"(ahi[1]), "=r"(ahi[2]), "=r"(ahi[3])
                    : "r"(base + sub + so));
                asm volatile("ldmatrix.sync.aligned.m8n8.x4.shared.b16 {%0,%1,%2,%3}, [%4];"
                    : "=r"(alo[0]), "=r"(alo[1]), "=r"(alo[2]), "=r"(alo[3])
                    : "r"(base + A_LO_OFF + sub + so));
            }
            uint32_t b[2][4];
            #pragma unroll
            for (int nh = 0; nh < 2; nh++) {
                int krow = kfl * 16 + (lane & 7) + ((lane >> 3) & 1) * 8;
                int colByte = (warpN * 32 + nh * 16 + (lane >> 4) * 8) * 2;
                uint32_t so = sw_off(krow, colByte);
                asm volatile("ldmatrix.sync.aligned.m8n8.x4.trans.shared.b16 {%0,%1,%2,%3}, [%4];"
                    : "=r"(b[nh][0]), "=r"(b[nh][1]), "=r"(b[nh][2]), "=r"(b[nh][3])
                    : "r"(base + B_OFF + sub + so));
            }
            #pragma unroll
            for (int j = 0; j < 4; j++) {
                uint32_t b0 = b[j >> 1][(j & 1) * 2], b1 = b[j >> 1][(j & 1) * 2 + 1];
                asm volatile(
                    "mma.sync.aligned.m16n8k16.row.col.f32.f16.f16.f32 "
                    "{%0,%1,%2,%3}, {%4,%5,%6,%7}, {%8,%9}, {%0,%1,%2,%3};"
                    : "+f"(acc[j][0]), "+f"(acc[j][1]), "+f"(acc[j][2]), "+f"(acc[j][3])
                    : "r"(ahi[0]), "r"(ahi[1]), "r"(ahi[2]), "r"(ahi[3]), "r"(b0), "r"(b1));
                asm volatile(
                    "mma.sync.aligned.m16n8k16.row.col.f32.f16.f16.f32 "
                    "{%0,%1,%2,%3}, {%4,%5,%6,%7}, {%8,%9}, {%0,%1,%2,%3};"
                    : "+f"(acc[j][0]), "+f"(acc[j][1]), "+f"(acc[j][2]), "+f"(acc[j][3])
                    : "r"(alo[0]), "r"(alo[1]), "r"(alo[2]), "r"(alo[3]), "r"(b0), "r"(b1));
            }
        }
    }

    // ---- epilogue: leaky tanh; in-place fp32 state (tile-exclusive),
    //      emit fp16 hi/lo for next step ----
    __half* __restrict__ shiN = g_shi[pp ^ 1];
    __half* __restrict__ sloN = g_slo[pp ^ 1];
    #pragma unroll
    for (int j = 0; j < 4; j++)
        #pragma unroll
        for (int h = 0; h < 2; h++) {
            int row = rowBase + warpM * 16 + (lane >> 2) + 8 * h;
            int col = colBase + warpN * 32 + j * 8 + (lane & 3) * 2;
            long long idx = (long long)row * RES + col;
            float2 sold = *reinterpret_cast<float2*>(&g_state[idx]);
            float n0 = 0.5f * sold.x + 0.5f * fast_tanhf(acc[j][h * 2 + 0]);
            float n1 = 0.5f * sold.y + 0.5f * fast_tanhf(acc[j][h * 2 + 1]);
            *reinterpret_cast<float2*>(&g_state[idx]) = make_float2(n0, n1);
            __half h0 = __float2half(n0);
            __half h1 = __float2half(n1);
            __half2 hv; hv.x = h0; hv.y = h1;
            __half2 lv;
            lv.x = __float2half(n0 - __half2float(h0));
            lv.y = __float2half(n1 - __half2float(h1));
            *reinterpret_cast<__half2*>(&shiN[idx]) = hv;
            *reinterpret_cast<__half2*>(&sloN[idx]) = lv;
        }
}

// ---------------- output GEMM ----------------------------------------------
__global__ __launch_bounds__(64) void output_kernel(
    const float* __restrict__ Wout, float* __restrict__ out) {
    __shared__ float srow[RES];
    const int b = blockIdx.x;
    const int j = threadIdx.x;
    for (int k = j; k < RES; k += 64) srow[k] = g_state[b * RES + k];
    __syncthreads();
    float sum = 0.0f;
    #pragma unroll 8
    for (int k = 0; k < RES; k++)
        sum = fmaf(srow[k], Wout[k * OUTSZ + j], sum);
    out[b * OUTSZ + j] = sum;
}

// ---------------- launch ----------------------------------------------------
extern "C" void kernel_launch(void* const* d_in, const int* in_sizes, int n_in,
                              void* d_out, int out_size) {
    const float* input = (const float*)d_in[0];   // [512,512,64]
    const float* Wres  = (const float*)d_in[1];   // [1024,1024]
    const float* Win   = (const float*)d_in[2];   // [64,1024]
    const float* Wout  = (const float*)d_in[3];   // [1024,64]
    float* out = (float*)d_out;

    cudaFuncSetAttribute(step_kernel,
                         cudaFuncAttributeMaxDynamicSharedMemorySize,
                         NSLOT * STAGE_BYTES);

    prep_kernel<<<4096, 256>>>(input, Wres, Win);   // my-index 0

    dim3 grid(RES / 64, BATCH / 64);   // (16, 8) = 128 CTAs
    for (int t = 0; t < SEQLEN; t++)   // my-index 1..512 (t=2 -> ncu slot 5)
        step_kernel<<<grid, 256, NSLOT * STAGE_BYTES>>>(t);

    output_kernel<<<BATCH, 64>>>(Wout, out);
}